// round 17
// baseline (speedup 1.0000x reference)
#include <cuda_runtime.h>
#include <cuda_fp16.h>
#include <math.h>
#include <stdint.h>

#define S_LEN 4096
#define HID   2048
#define NHEAD 16
#define DHEAD 128
#define W_SZ  ((size_t)HID * HID)

// ---------------- scratch (device globals; no allocations allowed) ----------
__device__ float g_Q[(size_t)S_LEN * HID];
__device__ float g_K[(size_t)S_LEN * HID];
__device__ __align__(16) __half g_Xh[(size_t)S_LEN * HID];      // X fp16 (A-side single)
__device__ __align__(16) __half g_Wh[4 * W_SZ];                 // W hi (B-side)
__device__ __align__(16) __half g_Wl[4 * W_SZ];                 // W lo
__device__ __align__(16) __half g_Aoh[(size_t)S_LEN * HID];     // attn out fp16 single
__device__ __align__(16) __half g_Qbh[(size_t)S_LEN * HID];     // rope'd Q fp16 (scaled)
__device__ __align__(16) __half g_Kbh[(size_t)S_LEN * HID];     // rope'd K hi
__device__ __align__(16) __half g_Kbl[(size_t)S_LEN * HID];     // rope'd K lo
__device__ __align__(16) __half g_Vbh[(size_t)S_LEN * HID];     // V fp16 (single)
__device__ int g_minpos;

// ---------------- PTX helpers (all sm_80-era: valid on compute_103) ---------
__device__ __forceinline__ uint32_t smem_u32(const void* p) {
    uint32_t a;
    asm("{ .reg .u64 t; cvta.to.shared.u64 t, %1; cvt.u32.u64 %0, t; }"
        : "=r"(a) : "l"(p));
    return a;
}

__device__ __forceinline__ void cp16(uint32_t saddr, const void* g) {
    asm volatile("cp.async.cg.shared.global [%0], [%1], 16;"
                 :: "r"(saddr), "l"(g) : "memory");
}
__device__ __forceinline__ void cp_commit() {
    asm volatile("cp.async.commit_group;" ::: "memory");
}
template <int N>
__device__ __forceinline__ void cp_wait() {
    asm volatile("cp.async.wait_group %0;" :: "n"(N) : "memory");
}

#define LDSM_X4(r, addr) \
    asm volatile("ldmatrix.sync.aligned.m8n8.x4.shared.b16 {%0,%1,%2,%3}, [%4];" \
                 : "=r"((r)[0]), "=r"((r)[1]), "=r"((r)[2]), "=r"((r)[3]) \
                 : "r"(addr))

#define LDSM_X4T(r, addr) \
    asm volatile("ldmatrix.sync.aligned.m8n8.x4.trans.shared.b16 {%0,%1,%2,%3}, [%4];" \
                 : "=r"((r)[0]), "=r"((r)[1]), "=r"((r)[2]), "=r"((r)[3]) \
                 : "r"(addr))

__device__ __forceinline__ void mma_f16(float* c, const uint32_t* a,
                                        uint32_t b0, uint32_t b1) {
    asm volatile(
        "mma.sync.aligned.m16n8k16.row.col.f32.f16.f16.f32 "
        "{%0,%1,%2,%3}, {%4,%5,%6,%7}, {%8,%9}, {%0,%1,%2,%3};"
        : "+f"(c[0]), "+f"(c[1]), "+f"(c[2]), "+f"(c[3])
        : "r"(a[0]), "r"(a[1]), "r"(a[2]), "r"(a[3]), "r"(b0), "r"(b1));
}

__device__ __forceinline__ uint32_t swz(uint32_t boff) {   // SW128-style
    return boff ^ ((boff >> 3) & 0x70);
}

__device__ __forceinline__ uint32_t pack_h2(float x, float y) {
    __half2 h = __floats2half2_rn(x, y);
    return *reinterpret_cast<uint32_t*>(&h);
}

__device__ __forceinline__ void pack_hl_f16(float x, float y,
                                            uint32_t& h, uint32_t& l) {
    __half2 hh = __floats2half2_rn(x, y);
    h = *reinterpret_cast<uint32_t*>(&hh);
    __half2 ll = __floats2half2_rn(x - __low2float(hh), y - __high2float(hh));
    l = *reinterpret_cast<uint32_t*>(&ll);
}

__device__ __forceinline__ float ex2(float x) {
    float y;
    asm("ex2.approx.ftz.f32 %0, %1;" : "=f"(y) : "f"(x));
    return y;
}

// ---------------- min(position_ids)  (JAX demotes int64->int32) -------------
__global__ void minpos_kernel(const int* __restrict__ pos, int n)
{
    __shared__ int sm[256];
    int v = 0x7fffffff;
    for (int i = threadIdx.x; i < n; i += 256) {
        int p = pos[i];
        v = (p < v) ? p : v;
    }
    sm[threadIdx.x] = v;
    __syncthreads();
    for (int s = 128; s > 0; s >>= 1) {
        if (threadIdx.x < s) {
            int o = sm[threadIdx.x + s];
            if (o < sm[threadIdx.x]) sm[threadIdx.x] = o;
        }
        __syncthreads();
    }
    if (threadIdx.x == 0) g_minpos = sm[0];
}

// ---------------- fp32 -> fp16 conversions -----------------------------------
__global__ void split_w4_kernel(const float* __restrict__ W0,
                                const float* __restrict__ W1,
                                const float* __restrict__ W2,
                                const float* __restrict__ W3,
                                __half* __restrict__ hi,
                                __half* __restrict__ lo, int n4per)
{
    int i = blockIdx.x * blockDim.x + threadIdx.x;
    if (i >= 4 * n4per) return;
    int w = i / n4per;
    int j = i - w * n4per;
    const float* src = (w == 0) ? W0 : (w == 1) ? W1 : (w == 2) ? W2 : W3;
    float4 v = ((const float4*)src)[j];
    uint32_t h0, l0, h1, l1;
    pack_hl_f16(v.x, v.y, h0, l0);
    pack_hl_f16(v.z, v.w, h1, l1);
    ((uint2*)hi)[i] = make_uint2(h0, h1);
    ((uint2*)lo)[i] = make_uint2(l0, l1);
}

__global__ void conv_h_kernel(const float* __restrict__ x,
                              __half* __restrict__ h, int n4)
{
    int i = blockIdx.x * blockDim.x + threadIdx.x;
    if (i >= n4) return;
    float4 v = ((const float4*)x)[i];
    ((uint2*)h)[i] = make_uint2(pack_h2(v.x, v.y), pack_h2(v.z, v.w));
}

// ---------------- mma.sync fp16 2-pass GEMM core: C = A * B^T ---------------
// A fp16 single; B fp16 hi/lo. Tile 128x128, K chunks of 64, 4-stage pipeline.
// mma issued in two independent 16-mma sweeps (bh then bl) -> no RAW chains.
#define MT_TILE  16384                       // 128 rows x 64 fp16 (128B rows)
#define MT_STAGE (3 * MT_TILE)               // A, Bh, Bl = 48K
#define MT_SMEM  (4 * MT_STAGE)              // 196608 B (4 stages)

__device__ __forceinline__ void mt_prefetch(
    uint32_t st, const __half* A,
    const __half* Bh, const __half* Bl,
    int m0, int n0, int k0, int K, int tid)
{
#pragma unroll
    for (int i = 0; i < 4; ++i) {
        int idx = tid + i * 256;             // 0..1023
        int r   = idx >> 3;
        int s   = idx & 7;
        uint32_t sw = swz(r * 128 + s * 16);
        size_t ga = (size_t)(m0 + r) * K + k0 + s * 8;
        size_t gb = (size_t)(n0 + r) * K + k0 + s * 8;
        cp16(st + sw,               A  + ga);
        cp16(st + MT_TILE + sw,     Bh + gb);
        cp16(st + 2 * MT_TILE + sw, Bl + gb);
    }
    cp_commit();
}

__device__ __forceinline__ void mt_mainloop(
    float acc[4][4][4], uint32_t sbase,
    const __half* A, const __half* Bh, const __half* Bl,
    int m0, int n0, int K, int tid)
{
    const int wid  = tid >> 5;
    const int lane = tid & 31;
    const int wm   = wid & 1;
    const int wn   = wid >> 1;

    const int nch = K >> 6;
    mt_prefetch(sbase, A, Bh, Bl, m0, n0, 0, K, tid);
    mt_prefetch(sbase + MT_STAGE, A, Bh, Bl, m0, n0, 64, K, tid);

    for (int c = 0; c < nch; ++c) {
        if (c + 2 < nch) {
            mt_prefetch(sbase + ((c + 2) & 3) * MT_STAGE,
                        A, Bh, Bl, m0, n0, (c + 2) << 6, K, tid);
            cp_wait<2>();
        } else if (c + 1 < nch) {
            cp_wait<1>();
        } else {
            cp_wait<0>();
        }
        __syncthreads();   // all threads' stage-c copies visible; with 4 stages
                           // the stage written at iter c was last read at c-2,
                           // already fenced by iter c-1's barrier -> no tail sync

        const uint32_t sA = sbase + (c & 3) * MT_STAGE;
        const uint32_t sB = sA + MT_TILE;

        const int a_row = wm * 64 + (lane & 15);
        const int a_sg  = lane >> 4;
        const int b_row = wn * 32 + ((lane >> 4) << 3) + (lane & 7);
        const int b_sg  = (lane >> 3) & 1;

#pragma unroll
        for (int ks = 0; ks < 4; ++ks) {
            uint32_t ah[4][4], bh[2][4], bl[2][4];
#pragma unroll
            for (int i = 0; i < 4; ++i) {
                uint32_t off = swz((a_row + i * 16) * 128 + (2 * ks + a_sg) * 16);
                LDSM_X4(ah[i], sA + off);
            }
#pragma unroll
            for (int jp = 0; jp < 2; ++jp) {
                uint32_t off = swz((b_row + jp * 16) * 128 + (2 * ks + b_sg) * 16);
                LDSM_X4(bh[jp], sB + off);
                LDSM_X4(bl[jp], sB + MT_TILE + off);
            }
            // sweep 1: 16 independent mma on Bh
#pragma unroll
            for (int i = 0; i < 4; ++i)
#pragma unroll
                for (int j = 0; j < 4; ++j)
                    mma_f16(acc[i][j], ah[i],
                            bh[j >> 1][(j & 1) * 2], bh[j >> 1][(j & 1) * 2 + 1]);
            // sweep 2: 16 independent mma on Bl (same per-acc order as before)
#pragma unroll
            for (int i = 0; i < 4; ++i)
#pragma unroll
                for (int j = 0; j < 4; ++j)
                    mma_f16(acc[i][j], ah[i],
                            bl[j >> 1][(j & 1) * 2], bl[j >> 1][(j & 1) * 2 + 1]);
        }
    }
}

// Fused QKV GEMM: B = [Wq;Wk;Wv] (6144 rows). Q,K -> fp32; V -> fp16 single.
__global__ __launch_bounds__(256) void gemm_qkv_kernel(
    const __half* __restrict__ A,
    const __half* __restrict__ Bh, const __half* __restrict__ Bl,
    float* __restrict__ Qf, float* __restrict__ Kf,
    __half* __restrict__ Vh, int K)
{
    extern __shared__ __align__(1024) char smc[];
    const uint32_t sbase = smem_u32(smc);
    const int tid  = threadIdx.x;
    const int wid  = tid >> 5;
    const int lane = tid & 31;
    const int m0 = blockIdx.y * 128;
    const int n0 = blockIdx.x * 128;

    float acc[4][4][4];
#pragma unroll
    for (int i = 0; i < 4; i++)
#pragma unroll
        for (int j = 0; j < 4; j++)
#pragma unroll
            for (int r = 0; r < 4; r++) acc[i][j][r] = 0.f;

    mt_mainloop(acc, sbase, A, Bh, Bl, m0, n0, K, tid);

    const int wm = wid & 1, wn = wid >> 1;
#pragma unroll
    for (int i = 0; i < 4; ++i) {
        int row = m0 + wm * 64 + i * 16 + (lane >> 2);
#pragma unroll
        for (int j = 0; j < 4; ++j) {
            int col = n0 + wn * 32 + j * 8 + (lane & 3) * 2;
            int cc  = col & 2047;
            size_t o0 = (size_t)row * HID + cc;
            size_t o1 = (size_t)(row + 8) * HID + cc;
            if (col < 4096) {
                float* dst = (col < 2048) ? Qf : Kf;
                *(float2*)(dst + o0) = make_float2(acc[i][j][0], acc[i][j][1]);
                *(float2*)(dst + o1) = make_float2(acc[i][j][2], acc[i][j][3]);
            } else {
                *(uint32_t*)(Vh + o0) = pack_h2(acc[i][j][0], acc[i][j][1]);
                *(uint32_t*)(Vh + o1) = pack_h2(acc[i][j][2], acc[i][j][3]);
            }
        }
    }
}

// Plain GEMM (fp32 out): final Wo projection.
__global__ __launch_bounds__(256) void gemm_mma_kernel(
    const __half* __restrict__ A,
    const __half* __restrict__ Bh, const __half* __restrict__ Bl,
    float* __restrict__ C, int M, int N, int K)
{
    extern __shared__ __align__(1024) char smc[];
    const uint32_t sbase = smem_u32(smc);
    const int tid  = threadIdx.x;
    const int wid  = tid >> 5;
    const int lane = tid & 31;
    const int m0 = blockIdx.y * 128;
    const int n0 = blockIdx.x * 128;

    float acc[4][4][4];
#pragma unroll
    for (int i = 0; i < 4; i++)
#pragma unroll
        for (int j = 0; j < 4; j++)
#pragma unroll
            for (int r = 0; r < 4; r++) acc[i][j][r] = 0.f;

    mt_mainloop(acc, sbase, A, Bh, Bl, m0, n0, K, tid);

    const int wm = wid & 1, wn = wid >> 1;
#pragma unroll
    for (int i = 0; i < 4; ++i) {
        int row = m0 + wm * 64 + i * 16 + (lane >> 2);
#pragma unroll
        for (int j = 0; j < 4; ++j) {
            int col = n0 + wn * 32 + j * 8 + (lane & 3) * 2;
            *(float2*)(C + (size_t)row * N + col) =
                make_float2(acc[i][j][0], acc[i][j][1]);
            *(float2*)(C + (size_t)(row + 8) * N + col) =
                make_float2(acc[i][j][2], acc[i][j][3]);
        }
    }
}

// ---------------- RoPE + fp16 convert (Q scaled by scale*log2e; K hi/lo) ----
__global__ void rope_split_kernel(const float* __restrict__ Q,
                                  const float* __restrict__ K,
                                  const int* __restrict__ pos,
                                  __half* __restrict__ Qh,
                                  __half* __restrict__ Kh,
                                  __half* __restrict__ Kl)
{
    int s = blockIdx.x;
    int t = threadIdx.x;          // 1024 threads: (h, d<64)
    int h = t >> 6;
    int d = t & 63;

    const float QSC = (float)(0.08838834764831845 * 1.4426950408889634);

    float tp = (float)(pos[s] - g_minpos);
    float invf = (float)exp(-log(10000.0) * ((double)(2 * d) / 128.0));
    float ang = tp * invf;
    float c, sn;
    sincosf(ang, &sn, &c);

    size_t base = (size_t)s * HID + h * DHEAD;
    float q1 = Q[base + d], q2 = Q[base + d + 64];
    float k1 = K[base + d], k2 = K[base + d + 64];
    float qa = (q1 * c - q2 * sn) * QSC, qb = (q2 * c + q1 * sn) * QSC;
    float ka = k1 * c - k2 * sn, kb = k2 * c + k1 * sn;

    Qh[base + d]      = __float2half(qa);
    Qh[base + d + 64] = __float2half(qb);
    __half kh;
    kh = __float2half(ka); Kh[base + d] = kh;
    Kl[base + d]      = __float2half(ka - __half2float(kh));
    kh = __float2half(kb); Kh[base + d + 64] = kh;
    Kl[base + d + 64] = __float2half(kb - __half2float(kh));
}

// ---------------- tensor-core flash attention --------------------------------
// CTA = 128 threads (4 warps x 16 q-rows), q-tile 64, k-block 64,
// K hi/lo 2-pass (independent sweeps), V fp16 1-pass. 2 CTAs/SM.
// smem: Q 16K @0 | K stages 2x32K @16K | V stages 2x16K @80K = 114688 B.
#define AT_SQ  0
#define AT_SK  16384
#define AT_SV  81920
#define AT_SMEM 114688

__device__ __forceinline__ void at_prefetch_kv(
    uint32_t sb, int stage, const __half* Kh, const __half* Kl,
    const __half* Vh, int k0, int h, int tid)
{
    const uint32_t sK = sb + AT_SK + stage * 32768;
    const uint32_t sV = sb + AT_SV + stage * 16384;
#pragma unroll
    for (int i = 0; i < 16; ++i) {            // K: 2048 cp16 (hi + lo)
        int idx = tid + i * 128;
        int hl = idx >> 10, rem = idx & 1023;
        int r = rem >> 4, dc = rem & 15;
        uint32_t sa = sK + hl * 16384 + (dc >> 3) * 8192
                    + swz(r * 128 + (dc & 7) * 16);
        const __half* g = hl ? Kl : Kh;
        cp16(sa, g + (size_t)(k0 + r) * HID + h * DHEAD + dc * 8);
    }
#pragma unroll
    for (int i = 0; i < 8; ++i) {             // V: 1024 cp16 (single)
        int idx = tid + i * 128;
        int r = idx >> 4, dc = idx & 15;
        uint32_t sa = sV + (dc >> 3) * 8192 + swz(r * 128 + (dc & 7) * 16);
        cp16(sa, Vh + (size_t)(k0 + r) * HID + h * DHEAD + dc * 8);
    }
    cp_commit();
}

__global__ __launch_bounds__(128, 2) void attn_mma_kernel(
    const __half* __restrict__ Qh,
    const __half* __restrict__ Kh, const __half* __restrict__ Kl,
    const __half* __restrict__ Vh,
    __half* __restrict__ Oh)
{
    extern __shared__ __align__(1024) char smb[];
    const uint32_t sb = smem_u32(smb);
    const int tid  = threadIdx.x;
    const int wid  = tid >> 5;                          // 0..3
    const int lane = tid & 31;
    const int qb = (int)(gridDim.x - 1 - blockIdx.x);   // big blocks first
    const int h  = blockIdx.y;
    const int q0 = qb * 64;
    const int nkb = qb + 1;                             // k-blocks of 64
    const float MASKC = -1.4426950e9f;                  // -1e9 * log2(e)

    // Q tile (fp16 single, 64 rows): 1024 cp16, loaded once
#pragma unroll
    for (int i = 0; i < 8; ++i) {
        int idx = tid + i * 128;
        int r = idx >> 4, dc = idx & 15;
        uint32_t sa = sb + AT_SQ + (dc >> 3) * 8192
                    + swz(r * 128 + (dc & 7) * 16);
        cp16(sa, Qh + (size_t)(q0 + r) * HID + h * DHEAD + dc * 8);
    }
    at_prefetch_kv(sb, 0, Kh, Kl, Vh, 0, h, tid);       // commits Q + stage0

    float o[16][4];
#pragma unroll
    for (int t = 0; t < 16; ++t)
#pragma unroll
        for (int r = 0; r < 4; ++r) o[t][r] = 0.f;
    float m0r = -INFINITY, m1r = -INFINITY, l0r = 0.f, l1r = 0.f;

    const int qrow0 = q0 + wid * 16 + (lane >> 2);
    const int qrow1 = qrow0 + 8;

    for (int c = 0; c < nkb; ++c) {
        if (c + 1 < nkb) {
            at_prefetch_kv(sb, (c + 1) & 1, Kh, Kl, Vh, (c + 1) * 64, h, tid);
            cp_wait<1>();
        } else {
            cp_wait<0>();
        }
        __syncthreads();

        const uint32_t sK = sb + AT_SK + (c & 1) * 32768;
        const uint32_t sV = sb + AT_SV + (c & 1) * 16384;
        const int k0 = c * 64;

        // ---- S = Q K^T  (64x64; Kh sweep then Kl sweep, no RAW chains) ----
        float sacc[8][4];
#pragma unroll
        for (int j = 0; j < 8; ++j)
#pragma unroll
            for (int r = 0; r < 4; ++r) sacc[j][r] = 0.f;

#pragma unroll
        for (int ks = 0; ks < 8; ++ks) {
            const int kh = ks >> 2, sg = ks & 3;
            uint32_t a[4], bh[4][4], bl[4][4];
            uint32_t qoff = kh * 8192 +
                swz((wid * 16 + (lane & 15)) * 128 + (2 * sg + (lane >> 4)) * 16);
            LDSM_X4(a, sb + AT_SQ + qoff);
#pragma unroll
            for (int ng = 0; ng < 4; ++ng) {
                uint32_t koff = kh * 8192 +
                    swz((ng * 16 + ((lane >> 4) << 3) + (lane & 7)) * 128 +
                        (2 * sg + ((lane >> 3) & 1)) * 16);
                LDSM_X4(bh[ng], sK + koff);
                LDSM_X4(bl[ng], sK + 16384 + koff);
            }
            // sweep 1: 8 independent mma on Kh
#pragma unroll
            for (int ng = 0; ng < 4; ++ng) {
                mma_f16(sacc[2 * ng],     a, bh[ng][0], bh[ng][1]);
                mma_f16(sacc[2 * ng + 1], a, bh[ng][2], bh[ng][3]);
            }
            // sweep 2: 8 independent mma on Kl (same per-acc order)
#pragma unroll
            for (int ng = 0; ng < 4; ++ng) {
                mma_f16(sacc[2 * ng],     a, bl[ng][0], bl[ng][1]);
                mma_f16(sacc[2 * ng + 1], a, bl[ng][2], bl[ng][3]);
            }
        }

        // ---- causal mask (diagonal block only) + online softmax in exp2 ----
        if ((k0 + 63) > q0) {
#pragma unroll
            for (int j = 0; j < 8; ++j) {
                int col = k0 + j * 8 + (lane & 3) * 2;
                if (col     > qrow0) sacc[j][0] += MASKC;
                if (col + 1 > qrow0) sacc[j][1] += MASKC;
                if (col     > qrow1) sacc[j][2] += MASKC;
                if (col + 1 > qrow1) sacc[j][3] += MASKC;
            }
        }
        float mx0 = -INFINITY, mx1 = -INFINITY;
#pragma unroll
        for (int j = 0; j < 8; ++j) {
            mx0 = fmaxf(mx0, fmaxf(sacc[j][0], sacc[j][1]));
            mx1 = fmaxf(mx1, fmaxf(sacc[j][2], sacc[j][3]));
        }
        mx0 = fmaxf(mx0, __shfl_xor_sync(0xffffffffu, mx0, 1));
        mx0 = fmaxf(mx0, __shfl_xor_sync(0xffffffffu, mx0, 2));
        mx1 = fmaxf(mx1, __shfl_xor_sync(0xffffffffu, mx1, 1));
        mx1 = fmaxf(mx1, __shfl_xor_sync(0xffffffffu, mx1, 2));

        float mn0 = fmaxf(m0r, mx0), mn1 = fmaxf(m1r, mx1);
        float fac0 = ex2(m0r - mn0), fac1 = ex2(m1r - mn1);
        m0r = mn0; m1r = mn1;

        float ls0 = 0.f, ls1 = 0.f;
#pragma unroll
        for (int j = 0; j < 8; ++j) {
            sacc[j][0] = ex2(sacc[j][0] - mn0);
            sacc[j][1] = ex2(sacc[j][1] - mn0);
            sacc[j][2] = ex2(sacc[j][2] - mn1);
            sacc[j][3] = ex2(sacc[j][3] - mn1);
            ls0 += sacc[j][0] + sacc[j][1];
            ls1 += sacc[j][2] + sacc[j][3];
        }
        ls0 += __shfl_xor_sync(0xffffffffu, ls0, 1);
        ls0 += __shfl_xor_sync(0xffffffffu, ls0, 2);
        ls1 += __shfl_xor_sync(0xffffffffu, ls1, 1);
        ls1 += __shfl_xor_sync(0xffffffffu, ls1, 2);
        l0r = l0r * fac0 + ls0;
        l1r = l1r * fac1 + ls1;

#pragma unroll
        for (int t = 0; t < 16; ++t) {
            o[t][0] *= fac0; o[t][1] *= fac0;
            o[t][2] *= fac1; o[t][3] *= fac1;
        }

        // ---- O += P V  (P fp16 single; V fp16 single: 1 pass) ----
#pragma unroll
        for (int ks = 0; ks < 4; ++ks) {
            uint32_t p[4];
            p[0] = pack_h2(sacc[2 * ks][0],     sacc[2 * ks][1]);
            p[1] = pack_h2(sacc[2 * ks][2],     sacc[2 * ks][3]);
            p[2] = pack_h2(sacc[2 * ks + 1][0], sacc[2 * ks + 1][1]);
            p[3] = pack_h2(sacc[2 * ks + 1][2], sacc[2 * ks + 1][3]);
#pragma unroll
            for (int ng = 0; ng < 8; ++ng) {
                uint32_t vh[4];
                uint32_t voff = (ng >> 2) * 8192 +
                    swz((ks * 16 + (lane & 15)) * 128 +
                        (ng & 3) * 32 + (lane >> 4) * 16);
                LDSM_X4T(vh, sV + voff);
                mma_f16(o[2 * ng],     p, vh[0], vh[1]);
                mma_f16(o[2 * ng + 1], p, vh[2], vh[3]);
            }
        }
        __syncthreads();
    }

    // ---- normalize + write fp16 single (feeds Wo GEMM A-side) ----
    float inv0 = 1.f / l0r, inv1 = 1.f / l1r;
#pragma unroll
    for (int t = 0; t < 16; ++t) {
        size_t col = h * DHEAD + t * 8 + (lane & 3) * 2;
        *(uint32_t*)(Oh + (size_t)qrow0 * HID + col) =
            pack_h2(o[t][0] * inv0, o[t][1] * inv0);
        *(uint32_t*)(Oh + (size_t)qrow1 * HID + col) =
            pack_h2(o[t][2] * inv1, o[t][3] * inv1);
    }
}

// ---------------- launch ----------------------------------------------------
extern "C" void kernel_launch(void* const* d_in, const int* in_sizes, int n_in,
                              void* d_out, int out_size)
{
    const float* X    = (const float*)d_in[0];
    const int*   pos  = (const int*)d_in[2];   // JAX x64 disabled: int32
    const float* Wq   = (const float*)d_in[3];
    const float* Wk   = (const float*)d_in[4];
    const float* Wv   = (const float*)d_in[5];
    const float* Wo   = (const float*)d_in[6];
    float*       out  = (float*)d_out;

    float *Qp, *Kp;
    __half *Xh, *Wh, *Wl, *Aoh, *Qbh, *Kbh, *Kbl, *Vbh;
    cudaGetSymbolAddress((void**)&Qp, g_Q);
    cudaGetSymbolAddress((void**)&Kp, g_K);
    cudaGetSymbolAddress((void**)&Xh, g_Xh);
    cudaGetSymbolAddress((void**)&Wh, g_Wh);
    cudaGetSymbolAddress((void**)&Wl, g_Wl);
    cudaGetSymbolAddress((void**)&Aoh, g_Aoh);
    cudaGetSymbolAddress((void**)&Qbh, g_Qbh);
    cudaGetSymbolAddress((void**)&Kbh, g_Kbh);
    cudaGetSymbolAddress((void**)&Kbl, g_Kbl);
    cudaGetSymbolAddress((void**)&Vbh, g_Vbh);

    minpos_kernel<<<1, 256>>>(pos, S_LEN);

    const int xn4 = (S_LEN * HID) / 4;
    const int wn4 = (HID * HID) / 4;
    conv_h_kernel<<<xn4 / 256, 256>>>(X, Xh, xn4);
    split_w4_kernel<<<(4 * wn4) / 256, 256>>>(Wq, Wk, Wv, Wo, Wh, Wl, wn4);

    cudaFuncSetAttribute(gemm_qkv_kernel,
                         cudaFuncAttributeMaxDynamicSharedMemorySize, MT_SMEM);
    cudaFuncSetAttribute(gemm_mma_kernel,
                         cudaFuncAttributeMaxDynamicSharedMemorySize, MT_SMEM);

    // fused QKV: B has 6144 rows (Wq|Wk|Wv contiguous in g_Wh/g_Wl)
    dim3 gq(3 * HID / 128, S_LEN / 128);       // (48, 32)
    gemm_qkv_kernel<<<gq, 256, MT_SMEM>>>(Xh, Wh, Wl, Qp, Kp, Vbh, HID);

    rope_split_kernel<<<S_LEN, 1024>>>(Qp, Kp, pos, Qbh, Kbh, Kbl);

    cudaFuncSetAttribute(attn_mma_kernel,
                         cudaFuncAttributeMaxDynamicSharedMemorySize, AT_SMEM);
    dim3 ag(S_LEN / 64, NHEAD);                // (64, 16)
    attn_mma_kernel<<<ag, 128, AT_SMEM>>>(Qbh, Kbh, Kbl, Vbh, Aoh);

    dim3 gg(HID / 128, S_LEN / 128);           // (16, 32)
    gemm_mma_kernel<<<gg, 256, MT_SMEM>>>(Aoh, Wh + 3 * W_SZ, Wl + 3 * W_SZ,
                                          out, S_LEN, HID, HID);
}